// round 17
// baseline (speedup 1.0000x reference)
#include <cuda_runtime.h>
#include <cuda_fp16.h>
#include <cstdint>

#define B_ 8
#define N_ 2048
#define D_ 128
#define CK 32                 // gemm1 k per chunk
#define NCK1 32               // gemm1 chunks per CTA (split-K=2: 32 x 32 = 1024)
#define SHALF (B_ * N_ * D_)
#define APITCH 136            // gemm1 A: halfs per k-row (128 j + pad) -> 272B
#define EPITCH 136            // gemm1 B(emb): halfs per k-row (128 d + pad) -> 272B
#define BPITCH 24             // gemm2 W,X: halfs per row (16 k + pad) -> 48B

// gemm1 dynamic smem: 4 stages of sA then 4 stages of sE
#define ASTAGE_BYTES (CK * APITCH * 2)        // 8704
#define ESTAGE_BYTES (CK * EPITCH * 2)        // 8704
#define G1_SMEM (4 * ASTAGE_BYTES + 4 * ESTAGE_BYTES)   // 69632

// ---------------------------------------------------------------------------
// Device scratch (no runtime allocation allowed)
// ---------------------------------------------------------------------------
__device__ float g_S[2 * SHALF];        // two split-K partial sums (16 MB)
__device__ int   g_deg[B_ * N_];        // nnz per cost row

// ---------------------------------------------------------------------------
// helpers
// ---------------------------------------------------------------------------
__device__ __forceinline__ void hmma(float* c, const uint32_t* a, const uint32_t* b) {
    asm volatile(
        "mma.sync.aligned.m16n8k16.row.col.f32.f16.f16.f32 "
        "{%0,%1,%2,%3}, {%4,%5,%6,%7}, {%8,%9}, {%0,%1,%2,%3};"
        : "+f"(c[0]), "+f"(c[1]), "+f"(c[2]), "+f"(c[3])
        : "r"(a[0]), "r"(a[1]), "r"(a[2]), "r"(a[3]), "r"(b[0]), "r"(b[1]));
}
__device__ __forceinline__ void ldsm4(uint32_t* r, uint32_t addr) {
    asm volatile("ldmatrix.sync.aligned.m8n8.x4.shared.b16 {%0,%1,%2,%3}, [%4];"
                 : "=r"(r[0]), "=r"(r[1]), "=r"(r[2]), "=r"(r[3]) : "r"(addr));
}
__device__ __forceinline__ void ldsm4t(uint32_t* r, uint32_t addr) {
    asm volatile("ldmatrix.sync.aligned.m8n8.x4.trans.shared.b16 {%0,%1,%2,%3}, [%4];"
                 : "=r"(r[0]), "=r"(r[1]), "=r"(r[2]), "=r"(r[3]) : "r"(addr));
}
__device__ __forceinline__ uint32_t sm_addr(const void* p) {
    return (uint32_t)__cvta_generic_to_shared(p);
}
// exact fp32 -> fp16 hi/lo split of a float4, packed as half2 words
__device__ __forceinline__ void split_f4(float4 v, uint32_t& h0, uint32_t& h1,
                                         uint32_t& l0, uint32_t& l1) {
    __half2 a = __floats2half2_rn(v.x, v.y);
    __half2 b = __floats2half2_rn(v.z, v.w);
    float2 af = __half22float2(a), bf = __half22float2(b);
    __half2 c = __floats2half2_rn(v.x - af.x, v.y - af.y);
    __half2 d = __floats2half2_rn(v.z - bf.x, v.w - bf.y);
    h0 = *(uint32_t*)&a; h1 = *(uint32_t*)&b;
    l0 = *(uint32_t*)&c; l1 = *(uint32_t*)&d;
}
// fp32 float4 -> fp16 (single rounding), packed as 2 half2 words
__device__ __forceinline__ void cvt_f4(float4 v, uint32_t& h0, uint32_t& h1) {
    __half2 a = __floats2half2_rn(v.x, v.y);
    __half2 b = __floats2half2_rn(v.z, v.w);
    h0 = *(uint32_t*)&a; h1 = *(uint32_t*)&b;
}

// ---------------------------------------------------------------------------
// zero_deg: clear degree counters (prep2's transpose is gone — gemm1 now
// consumes emb directly via k-major smem + ldmatrix.trans)
// ---------------------------------------------------------------------------
__global__ void zero_deg_kernel() {
    int i = blockIdx.x * 512 + threadIdx.x;
    if (i < B_ * N_) g_deg[i] = 0;
}

// ---------------------------------------------------------------------------
// gemm1 on mma.sync, single-term fp16 x fp16, split-K=2, CK=32 chunks.
// C[j][d] += cost[k][j0+j] * fp16(emb[k][d]) over this CTA's K half (1024).
// CTA tile 128j x 128d, grid (16, 8, 2) = 256 CTAs -> 2 CTAs/SM.
// A (cost): k-major [k][j], ldsm4t (proven). B (emb): k-major [k][d] straight
// from emb's natural layout, ldsm4t with lane map rB=(lane&7)+((lane&8)?8:0),
// cB=(lane&16)?8:0 so x4 result regs pair adjacently per n8-block:
//   m0(l0-7):  k0-7 x n0-7   -> r0 = (n0-7, k0-7)
//   m1(l8-15): k8-15 x n0-7  -> r1 = (n0-7, k8-15)
//   m2(l16-23):k0-7 x n8-15  -> r2 = (n8-15,k0-7)
//   m3(l24-31):k8-15 x n8-15 -> r3 = (n8-15,k8-15)
// 4-stage ring, one barrier per two chunks (R15 schedule, proven).
// ---------------------------------------------------------------------------
__global__ __launch_bounds__(256, 2) void gemm1_mma_kernel(
    const float* __restrict__ cost, const float* __restrict__ emb)
{
    extern __shared__ __align__(16) char smem_dyn[];

    const int tid = threadIdx.x, lane = tid & 31, w = tid >> 5;
    const int b = blockIdx.y, j0 = blockIdx.x * 128;
    const int kz = blockIdx.z, kbase = kz * (N_ / 2);
    const float* cB = cost + (size_t)b * N_ * N_;
    const float* eB = emb + (size_t)b * N_ * D_;

    auto sA_st = [&](int st) -> __half* {
        return (__half*)(smem_dyn + st * ASTAGE_BYTES);
    };
    auto sE_st = [&](int st) -> __half* {
        return (__half*)(smem_dyn + 4 * ASTAGE_BYTES + st * ESTAGE_BYTES);
    };

    // load-role indices
    const int kkA = w;                 // warp loads cost rows kkA + 8q, q=0..3
    const int jq  = lane;
    const int kE  = tid >> 3;          // emb row within chunk (0..31)
    const int dE  = (tid & 7) * 16;    // 16-d segment

    // mma-role indices: warp tile 32m x 64n
    const int wm = w & 3, wn = w >> 2;
    const int m0w = wm * 32, n0w = wn * 64;
    const int rsel = (lane & 7) + ((lane & 16) ? 8 : 0);   // A k-row map
    const int csel = (lane & 8) ? 8 : 0;
    const int rB   = (lane & 7) + ((lane & 8) ? 8 : 0);    // B k-row map
    const int cBo  = (lane & 16) ? 8 : 0;

    float acc[2][8][4];
    #pragma unroll
    for (int mi = 0; mi < 2; mi++)
        #pragma unroll
        for (int ni = 0; ni < 8; ni++)
            #pragma unroll
            for (int q = 0; q < 4; q++) acc[mi][ni][q] = 0.f;

    // held chunk registers (single set, one-iteration live range)
    float4 ca[4]; float4 ev[4];
    auto load_chunk = [&](int c) {
        const int i0 = kbase + c * CK;
        #pragma unroll
        for (int q = 0; q < 4; q++)
            ca[q] = *(const float4*)(cB + (size_t)(i0 + kkA + 8 * q) * N_ + j0 + jq * 4);
        #pragma unroll
        for (int q = 0; q < 4; q++)
            ev[q] = *(const float4*)(eB + (size_t)(i0 + kE) * D_ + dE + 4 * q);
    };
    auto store_chunk = [&](int c) {
        const int i0 = kbase + c * CK;
        const int st = c & 3;
        __half* sA = sA_st(st);
        __half* sE = sE_st(st);
        #pragma unroll
        for (int q = 0; q < 4; q++) {
            const int kr = kkA + 8 * q;
            int cnt = (ca[q].x != 0.f) + (ca[q].y != 0.f) + (ca[q].z != 0.f) + (ca[q].w != 0.f);
            cnt = __reduce_add_sync(0xffffffffu, cnt);
            if (lane == q) atomicAdd(&g_deg[b * N_ + i0 + kr], cnt);
            uint32_t h0, h1;
            cvt_f4(ca[q], h0, h1);
            *(uint2*)&sA[kr * APITCH + jq * 4] = make_uint2(h0, h1);
        }
        #pragma unroll
        for (int q = 0; q < 4; q++) {
            uint32_t h0, h1;
            cvt_f4(ev[q], h0, h1);
            *(uint2*)&sE[kE * EPITCH + dE + 4 * q] = make_uint2(h0, h1);
        }
    };
    auto consume = [&](int c) {
        const int st = c & 3;
        __half* sA = sA_st(st);
        __half* sE = sE_st(st);
        #pragma unroll
        for (int ks = 0; ks < 2; ks++) {
            uint32_t ah[2][4], bh[4][4];
            #pragma unroll
            for (int mi = 0; mi < 2; mi++)
                ldsm4t(ah[mi], sm_addr(&sA[(ks * 16 + rsel) * APITCH + m0w + mi * 16 + csel]));
            #pragma unroll
            for (int nq = 0; nq < 4; nq++)
                ldsm4t(bh[nq], sm_addr(&sE[(ks * 16 + rB) * EPITCH + n0w + nq * 16 + cBo]));
            #pragma unroll
            for (int mi = 0; mi < 2; mi++)
                #pragma unroll
                for (int ni = 0; ni < 8; ni++)
                    hmma(acc[mi][ni], ah[mi], &bh[ni >> 1][(ni & 1) * 2]);
        }
    };

    // ---- prologue: chunks 0,1 -> stages 0,1; chunk 2 -> held regs ----
    load_chunk(0);
    store_chunk(0);
    load_chunk(1);
    store_chunk(1);
    load_chunk(2);
    __syncthreads();

    // ---- main loop: one barrier per pair of chunks ----
    for (int p = 0; p < NCK1 / 2; p++) {
        const int c = 2 * p;

        if (c + 2 < NCK1) store_chunk(c + 2);
        if (c + 3 < NCK1) load_chunk(c + 3);
        consume(c);
        if (c + 3 < NCK1) store_chunk(c + 3);
        if (c + 4 < NCK1) load_chunk(c + 4);
        consume(c + 1);
        __syncthreads();
    }

    // ---- epilogue: fragments -> g_S[kz][b][j][d] ----
    float* Sr = g_S + (size_t)kz * SHALF + ((size_t)(b * N_ + j0)) * D_;
    #pragma unroll
    for (int mi = 0; mi < 2; mi++) {
        int r = m0w + mi * 16 + (lane >> 2);
        #pragma unroll
        for (int ni = 0; ni < 8; ni++) {
            int cix = n0w + ni * 8 + 2 * (lane & 3);
            *(float2*)(Sr + (size_t)r * D_ + cix)       = make_float2(acc[mi][ni][0], acc[mi][ni][1]);
            *(float2*)(Sr + (size_t)(r + 8) * D_ + cix) = make_float2(acc[mi][ni][2], acc[mi][ni][3]);
        }
    }
}

// ---------------------------------------------------------------------------
// gemm2 on mma.sync fp16 hi/lo split (3 terms), distance-2 schedule:
//   out[n,d] = relu( sum_f X[n,f] * W[d,f] + bias[d] )
//   X[n,f] = (f < 128) ? emb[n,f] : (S0[n,f-128]+S1[n,f-128]) / degree[n]
// CTA tile 64n x 128d, K = 256 in 16 chunks, grid 256, 256 threads.
// ---------------------------------------------------------------------------
__global__ __launch_bounds__(256, 2) void gemm2_mma_kernel(
    const float* __restrict__ emb, const float* __restrict__ W,
    const float* __restrict__ bias, float* __restrict__ out)
{
    __shared__ __align__(16) __half sX[2][2][64 * BPITCH];    // [stage][hi/lo][n][f]
    __shared__ __align__(16) __half sW[2][2][128 * BPITCH];   // [stage][hi/lo][d][f]

    const int tid = threadIdx.x, lane = tid & 31, w = tid >> 5;
    const int gn0 = blockIdx.x * 64;

    // producer roles
    const int nX = tid >> 2, fqX = (tid & 3) * 4;   // X: row nX, f-quad fqX
    const int dW = tid & 127, qW = tid >> 7;        // W: row dW, 8-f half qW
    const float invdeg = 1.0f / (float)g_deg[gn0 + nX];

    // mma roles: warp tile 16m x 64n; 4 m-slots x 2 n-slots
    const int wm = w & 3, wn = w >> 2;
    const int m0w = wm * 16, n0w = wn * 64;
    const int rA = lane & 15, cA = (lane & 16) ? 8 : 0;          // A row-major map
    const int rsel = (lane & 7) + ((lane & 16) ? 8 : 0);         // B map (proven)
    const int csel = (lane & 8) ? 8 : 0;

    float acc[8][4];
    #pragma unroll
    for (int ni = 0; ni < 8; ni++)
        #pragma unroll
        for (int q = 0; q < 4; q++) acc[ni][q] = 0.f;

    // bias preload (per-thread columns)
    float2 bb[8];
    #pragma unroll
    for (int ni = 0; ni < 8; ni++) {
        int cix = n0w + ni * 8 + 2 * (lane & 3);
        bb[ni] = make_float2(bias[cix], bias[cix + 1]);
    }

    // held chunk registers
    float4 xv, wv0, wv1;
    auto load_c = [&](int k0) {
        if (k0 < D_) {
            xv = *(const float4*)(emb + (size_t)(gn0 + nX) * D_ + k0 + fqX);
        } else {
            const float* s0p = g_S + (size_t)(gn0 + nX) * D_ + (k0 - D_) + fqX;
            float4 a = *(const float4*)s0p;
            float4 bq = *(const float4*)(s0p + SHALF);
            xv = make_float4((a.x + bq.x) * invdeg, (a.y + bq.y) * invdeg,
                             (a.z + bq.z) * invdeg, (a.w + bq.w) * invdeg);
        }
        wv0 = *(const float4*)(W + (size_t)dW * 256 + k0 + qW * 8);
        wv1 = *(const float4*)(W + (size_t)dW * 256 + k0 + qW * 8 + 4);
    };
    auto store_c = [&](int st) {
        uint32_t h0, h1, l0, l1;
        split_f4(xv, h0, h1, l0, l1);
        *(uint2*)&sX[st][0][nX * BPITCH + fqX] = make_uint2(h0, h1);
        *(uint2*)&sX[st][1][nX * BPITCH + fqX] = make_uint2(l0, l1);
        split_f4(wv0, h0, h1, l0, l1);
        *(uint2*)&sW[st][0][dW * BPITCH + qW * 8] = make_uint2(h0, h1);
        *(uint2*)&sW[st][1][dW * BPITCH + qW * 8] = make_uint2(l0, l1);
        split_f4(wv1, h0, h1, l0, l1);
        *(uint2*)&sW[st][0][dW * BPITCH + qW * 8 + 4] = make_uint2(h0, h1);
        *(uint2*)&sW[st][1][dW * BPITCH + qW * 8 + 4] = make_uint2(l0, l1);
    };

    // ---- prologue ----
    load_c(0);
    store_c(0);
    load_c(16);
    __syncthreads();

    for (int c = 0; c < 16; c++) {
        const int s = c & 1;

        if (c + 1 < 16) store_c(s ^ 1);
        if (c + 2 < 16) load_c((c + 2) * 16);

        uint32_t ah[4], al[4], bh[4][4], bl[4][4];
        ldsm4(ah, sm_addr(&sX[s][0][(m0w + rA) * BPITCH + cA]));
        ldsm4(al, sm_addr(&sX[s][1][(m0w + rA) * BPITCH + cA]));
        #pragma unroll
        for (int nq = 0; nq < 4; nq++) {
            ldsm4(bh[nq], sm_addr(&sW[s][0][(n0w + nq * 16 + rsel) * BPITCH + csel]));
            ldsm4(bl[nq], sm_addr(&sW[s][1][(n0w + nq * 16 + rsel) * BPITCH + csel]));
        }
        #pragma unroll
        for (int ni = 0; ni < 8; ni++) {
            const uint32_t* BH = &bh[ni >> 1][(ni & 1) * 2];
            const uint32_t* BL = &bl[ni >> 1][(ni & 1) * 2];
            hmma(acc[ni], ah, BH);
            hmma(acc[ni], ah, BL);
            hmma(acc[ni], al, BH);
        }
        __syncthreads();
    }

    // epilogue: bias + relu + store
    const int r = m0w + (lane >> 2);
    #pragma unroll
    for (int ni = 0; ni < 8; ni++) {
        int cix = n0w + ni * 8 + 2 * (lane & 3);
        float* O0 = out + (size_t)(gn0 + r) * D_ + cix;
        float* O1 = out + (size_t)(gn0 + r + 8) * D_ + cix;
        *(float2*)O0 = make_float2(fmaxf(acc[ni][0] + bb[ni].x, 0.f),
                                   fmaxf(acc[ni][1] + bb[ni].y, 0.f));
        *(float2*)O1 = make_float2(fmaxf(acc[ni][2] + bb[ni].x, 0.f),
                                   fmaxf(acc[ni][3] + bb[ni].y, 0.f));
    }
}

// ---------------------------------------------------------------------------
extern "C" void kernel_launch(void* const* d_in, const int* in_sizes, int n_in,
                              void* d_out, int out_size)
{
    const float *emb = nullptr, *cost = nullptr, *W = nullptr, *bias = nullptr;
    for (int i = 0; i < n_in; i++) {
        int s = in_sizes[i];
        if      (s == B_ * N_ * N_) cost = (const float*)d_in[i];
        else if (s == B_ * N_ * D_) emb  = (const float*)d_in[i];
        else if (s == 2 * D_ * D_)  W    = (const float*)d_in[i];
        else if (s == D_)           bias = (const float*)d_in[i];
    }

    static bool attr_set = false;
    if (!attr_set) {
        cudaFuncSetAttribute(gemm1_mma_kernel,
                             cudaFuncAttributeMaxDynamicSharedMemorySize, G1_SMEM);
        attr_set = true;
    }

    zero_deg_kernel<<<32, 512>>>();
    gemm1_mma_kernel<<<dim3(16, 8, 2), 256, G1_SMEM>>>(cost, emb);
    gemm2_mma_kernel<<<256, 256>>>(emb, W, bias, (float*)d_out);
}